// round 8
// baseline (speedup 1.0000x reference)
#include <cuda_runtime.h>

#define B 64
#define CIN 512
#define HIDE 128
#define OP 512
#define HW 4096   // 64*64

__device__ float g_y[B * CIN];   // pooled values
__device__ int   g_done[B];      // per-batch completed-row counters (zero-init)

// ---------------------------------------------------------------------------
// Kernel 1: global average pool (proven 87.6%-DRAM body) + per-batch signal.
// One block per (b,c) row.
// ---------------------------------------------------------------------------
__global__ __launch_bounds__(256) void pool_kernel(const float* __restrict__ x,
                                                   float* __restrict__ y) {
    cudaTriggerProgrammaticLaunchCompletion();

    const int row = blockIdx.x;
    const float4* p = reinterpret_cast<const float4*>(x + (size_t)row * HW);
    const int t = threadIdx.x;

    float s = 0.0f;
#pragma unroll
    for (int i = 0; i < 4; i++) {
        float4 v = __ldcs(&p[t + i * 256]);
        s += (v.x + v.y) + (v.z + v.w);
    }
#pragma unroll
    for (int o = 16; o > 0; o >>= 1) s += __shfl_xor_sync(0xFFFFFFFFu, s, o);

    __shared__ float sm[8];
    if ((t & 31) == 0) sm[t >> 5] = s;
    __syncthreads();
    if (t < 8) {
        float v = sm[t];
#pragma unroll
        for (int o = 4; o > 0; o >>= 1) v += __shfl_xor_sync(0x000000FFu, v, o);
        if (t == 0) {
            y[row] = v * (1.0f / (float)HW);
            __threadfence();
            atomicAdd(&g_done[row >> 9], 1);
        }
    }
}

// ---------------------------------------------------------------------------
// Kernel 2: AGCA head, PDL-launched, per-batch spin. One block per batch,
// 256 threads. Runs concurrently with the pool; block b proceeds as soon as
// its 512 pooled rows are complete.
// ---------------------------------------------------------------------------
__global__ __launch_bounds__(256) void head_kernel(const float* __restrict__ W1,
                                                   const float* __restrict__ A2,
                                                   const float* __restrict__ w2p,
                                                   const float* __restrict__ w3p,
                                                   const float* __restrict__ W4,
                                                   float* __restrict__ out) {
    const int b    = blockIdx.x;
    const int tid  = threadIdx.x;
    const int wid  = tid >> 5;
    const int lane = tid & 31;

    __shared__ float ys[CIN];
    __shared__ float y1s[HIDE];
    __shared__ float a1s[HIDE];
    __shared__ float y3s[HIDE];
    __shared__ float red[8];

    // wait for this batch's 512 pooled rows
    if (tid == 0) {
        while (((volatile int*)g_done)[b] < CIN) __nanosleep(64);
        __threadfence();
    }
    __syncthreads();

    ys[tid]       = g_y[b * CIN + tid];
    ys[tid + 256] = g_y[b * CIN + tid + 256];
    __syncthreads();

    // ---- GEMV1: warp wid owns h in [wid*16, wid*16+16): 2 passes of 8 ----
#pragma unroll
    for (int pass = 0; pass < 2; pass++) {
        const int h0 = (wid << 4) + (pass << 3);
        float acc[8];
#pragma unroll
        for (int i = 0; i < 8; i++) acc[i] = 0.0f;
#pragma unroll
        for (int k = 0; k < CIN / 32; k++) {
            const int c = lane + (k << 5);
            const float yv = ys[c];
#pragma unroll
            for (int i = 0; i < 8; i++)
                acc[i] += yv * __ldg(&W1[(size_t)(h0 + i) * CIN + c]);
        }
#pragma unroll
        for (int o = 16; o > 0; o >>= 1)
#pragma unroll
            for (int i = 0; i < 8; i++)
                acc[i] += __shfl_xor_sync(0xFFFFFFFFu, acc[i], o);
        if (lane == 0)
#pragma unroll
            for (int i = 0; i < 8; i++) y1s[h0 + i] = acc[i];
    }
    __syncthreads();

    // ---- softmax(w2 * y1) over 128 channels (warps 0..3) ----
    const float w2 = __ldg(w2p);
    if (tid < HIDE) {
        const float z = w2 * y1s[tid];
        float m = z;
#pragma unroll
        for (int o = 16; o > 0; o >>= 1) m = fmaxf(m, __shfl_xor_sync(0xFFFFFFFFu, m, o));
        if (lane == 0) red[wid] = m;
    }
    __syncthreads();
    if (tid < HIDE) {
        const float m = fmaxf(fmaxf(red[0], red[1]), fmaxf(red[2], red[3]));
        const float e = expf(w2 * y1s[tid] - m);
        a1s[tid] = e;
        float ssum = e;
#pragma unroll
        for (int o = 16; o > 0; o >>= 1) ssum += __shfl_xor_sync(0xFFFFFFFFu, ssum, o);
        if (lane == 0) red[4 + wid] = ssum;
    }
    __syncthreads();

    // ---- y2/y3: h = tid (<128); A2 coalesced over h ----
    if (tid < HIDE) {
        const float ssum = (red[4] + red[5]) + (red[6] + red[7]);
        const float a1n = a1s[tid] / ssum;
        float t = y1s[tid] * a1n;
#pragma unroll 16
        for (int j = 0; j < HIDE; j++) t += y1s[j] * __ldg(&A2[j * HIDE + tid]);
        const float w3 = __ldg(w3p);
        y3s[tid] = fmaxf(w3 * t, 0.0f);
    }
    __syncthreads();

    // ---- GEMV4: warp wid owns o in [wid*64, wid*64+64): 8 passes of 8 ----
#pragma unroll
    for (int pass = 0; pass < 8; pass++) {
        const int o0 = (wid << 6) + (pass << 3);
        float acc[8];
#pragma unroll
        for (int i = 0; i < 8; i++) acc[i] = 0.0f;
#pragma unroll
        for (int k = 0; k < HIDE / 32; k++) {
            const int j = lane + (k << 5);
            const float yv = y3s[j];
#pragma unroll
            for (int i = 0; i < 8; i++)
                acc[i] += yv * __ldg(&W4[(size_t)(o0 + i) * HIDE + j]);
        }
#pragma unroll
        for (int off = 16; off > 0; off >>= 1)
#pragma unroll
            for (int i = 0; i < 8; i++)
                acc[i] += __shfl_xor_sync(0xFFFFFFFFu, acc[i], off);
        if (lane == 0) {
#pragma unroll
            for (int i = 0; i < 8; i++)
                out[b * OP + o0 + i] = 1.0f / (1.0f + expf(-acc[i]));
        }
    }

    // reset flag for next replay (stream-ordered: next pool launch cannot
    // overlap this kernel)
    __syncthreads();
    if (tid == 0) g_done[b] = 0;
}

extern "C" void kernel_launch(void* const* d_in, const int* in_sizes, int n_in,
                              void* d_out, int out_size) {
    const float* x  = (const float*)d_in[0];
    const float* W1 = (const float*)d_in[1];
    const float* A2 = (const float*)d_in[2];
    const float* w2 = (const float*)d_in[3];
    const float* w3 = (const float*)d_in[4];
    const float* W4 = (const float*)d_in[5];
    float* out = (float*)d_out;

    float* yscratch;
    cudaGetSymbolAddress((void**)&yscratch, g_y);

    pool_kernel<<<B * CIN, 256>>>(x, yscratch);

    // PDL: head launches while pool drains; each head block gates itself on
    // its own batch's completion counter.
    cudaLaunchConfig_t cfg = {};
    cfg.gridDim = dim3(B);
    cfg.blockDim = dim3(256);
    cfg.dynamicSmemBytes = 0;
    cfg.stream = 0;
    cudaLaunchAttribute attr[1];
    attr[0].id = cudaLaunchAttributeProgrammaticStreamSerialization;
    attr[0].val.programmaticStreamSerializationAllowed = 1;
    cfg.attrs = attr;
    cfg.numAttrs = 1;
    cudaLaunchKernelEx(&cfg, head_kernel, W1, A2, w2, w3, W4, out);
}

// round 9
// speedup vs baseline: 1.5921x; 1.5921x over previous
#include <cuda_runtime.h>

#define B 64
#define CIN 512
#define HIDE 128
#define OP 512
#define HW 4096   // 64*64

// scratch for pooled y [B, CIN]
__device__ float g_y[B * CIN];

__device__ __forceinline__ void prefetch_l2_last(const void* p) {
    asm volatile("prefetch.global.L2::evict_last [%0];" :: "l"(p));
}

// ---------------------------------------------------------------------------
// Kernel 0: weight prefetch into L2 with evict_last so the lines survive the
// pool's evict-first streaming. 18 blocks x 256 threads = 4608 x 128B lines
// = 576KB (W1 256KB + W4 256KB + A2 64KB). Triggers PDL immediately so the
// pool launches underneath it.
// ---------------------------------------------------------------------------
__global__ __launch_bounds__(256) void prefetch_kernel(const float* __restrict__ W1,
                                                       const float* __restrict__ A2,
                                                       const float* __restrict__ W4) {
    cudaTriggerProgrammaticLaunchCompletion();
    const int idx = blockIdx.x * 256 + threadIdx.x;  // 0..4607
    if (idx < 2048) {
        prefetch_l2_last((const char*)W1 + (size_t)idx * 128);
    } else if (idx < 4096) {
        prefetch_l2_last((const char*)W4 + (size_t)(idx - 2048) * 128);
    } else {
        prefetch_l2_last((const char*)A2 + (size_t)(idx - 4096) * 128);
    }
}

// ---------------------------------------------------------------------------
// Kernel 1: global average pool — EXACT proven body (87.6% DRAM). One block
// per (b,c) row of 4096 floats.
// ---------------------------------------------------------------------------
__global__ __launch_bounds__(256) void pool_kernel(const float* __restrict__ x,
                                                   float* __restrict__ y) {
    cudaTriggerProgrammaticLaunchCompletion();

    const int row = blockIdx.x;
    const float4* p = reinterpret_cast<const float4*>(x + (size_t)row * HW);
    const int t = threadIdx.x;

    float s = 0.0f;
#pragma unroll
    for (int i = 0; i < 4; i++) {
        float4 v = __ldcs(&p[t + i * 256]);
        s += (v.x + v.y) + (v.z + v.w);
    }
#pragma unroll
    for (int o = 16; o > 0; o >>= 1) s += __shfl_xor_sync(0xFFFFFFFFu, s, o);

    __shared__ float sm[8];
    if ((t & 31) == 0) sm[t >> 5] = s;
    __syncthreads();
    if (t < 8) {
        float v = sm[t];
#pragma unroll
        for (int o = 4; o > 0; o >>= 1) v += __shfl_xor_sync(0x000000FFu, v, o);
        if (t == 0) y[row] = v * (1.0f / (float)HW);
    }
}

// ---------------------------------------------------------------------------
// Kernel 2: fused AGCA head (R4-proven shape). One block per batch, 1024 thr.
// ---------------------------------------------------------------------------
__global__ __launch_bounds__(1024) void head_kernel(const float* __restrict__ y,
                                                    const float* __restrict__ W1,
                                                    const float* __restrict__ A2,
                                                    const float* __restrict__ w2p,
                                                    const float* __restrict__ w3p,
                                                    const float* __restrict__ W4,
                                                    float* __restrict__ out) {
    const int b    = blockIdx.x;
    const int tid  = threadIdx.x;
    const int wid  = tid >> 5;
    const int lane = tid & 31;

    cudaGridDependencySynchronize();

    __shared__ float ys[CIN];
    __shared__ float y1s[HIDE];
    __shared__ float a1s[HIDE];
    __shared__ float y3s[HIDE];
    __shared__ float red[8];

    if (tid < CIN) ys[tid] = y[b * CIN + tid];
    __syncthreads();

    // ---- GEMV1: warp wid -> h = wid*4 + {0..3}; batched loads ----
    {
        const int h0 = wid << 2;
        const float* r0 = W1 + (size_t)(h0 + 0) * CIN;
        const float* r1 = W1 + (size_t)(h0 + 1) * CIN;
        const float* r2 = W1 + (size_t)(h0 + 2) * CIN;
        const float* r3 = W1 + (size_t)(h0 + 3) * CIN;
        float a0 = 0.f, a1 = 0.f, a2 = 0.f, a3 = 0.f;
#pragma unroll
        for (int k = 0; k < CIN / 32; k++) {
            const int c = lane + (k << 5);
            const float yv = ys[c];
            a0 += yv * __ldg(r0 + c);
            a1 += yv * __ldg(r1 + c);
            a2 += yv * __ldg(r2 + c);
            a3 += yv * __ldg(r3 + c);
        }
#pragma unroll
        for (int o = 16; o > 0; o >>= 1) {
            a0 += __shfl_xor_sync(0xFFFFFFFFu, a0, o);
            a1 += __shfl_xor_sync(0xFFFFFFFFu, a1, o);
            a2 += __shfl_xor_sync(0xFFFFFFFFu, a2, o);
            a3 += __shfl_xor_sync(0xFFFFFFFFu, a3, o);
        }
        if (lane == 0) {
            y1s[h0 + 0] = a0; y1s[h0 + 1] = a1;
            y1s[h0 + 2] = a2; y1s[h0 + 3] = a3;
        }
    }
    __syncthreads();

    // ---- softmax(w2 * y1) over 128 channels (first 4 warps) ----
    const float w2 = __ldg(w2p);
    if (tid < HIDE) {
        const float z = w2 * y1s[tid];
        float m = z;
#pragma unroll
        for (int o = 16; o > 0; o >>= 1) m = fmaxf(m, __shfl_xor_sync(0xFFFFFFFFu, m, o));
        if (lane == 0) red[wid] = m;
    }
    __syncthreads();
    if (tid < HIDE) {
        const float m = fmaxf(fmaxf(red[0], red[1]), fmaxf(red[2], red[3]));
        const float e = expf(w2 * y1s[tid] - m);
        a1s[tid] = e;
        float ssum = e;
#pragma unroll
        for (int o = 16; o > 0; o >>= 1) ssum += __shfl_xor_sync(0xFFFFFFFFu, ssum, o);
        if (lane == 0) red[4 + wid] = ssum;
    }
    __syncthreads();

    // ---- y2/y3: h = tid (<128); A2 coalesced over h ----
    if (tid < HIDE) {
        const float ssum = (red[4] + red[5]) + (red[6] + red[7]);
        const float a1n = a1s[tid] / ssum;
        float t = y1s[tid] * a1n;
#pragma unroll 16
        for (int j = 0; j < HIDE; j++) t += y1s[j] * __ldg(&A2[j * HIDE + tid]);
        const float w3 = __ldg(w3p);
        y3s[tid] = fmaxf(w3 * t, 0.0f);
    }
    __syncthreads();

    // ---- GEMV4: warp wid owns outputs wid*16..wid*16+15 (2 passes of 8) ----
#pragma unroll
    for (int pass = 0; pass < 2; pass++) {
        const int o_base = (wid << 4) + (pass << 3);
        float acc[8];
#pragma unroll
        for (int i = 0; i < 8; i++) acc[i] = 0.0f;
#pragma unroll
        for (int k = 0; k < HIDE / 32; k++) {
            const int j = lane + (k << 5);
            const float yv = y3s[j];
#pragma unroll
            for (int i = 0; i < 8; i++)
                acc[i] += yv * __ldg(&W4[(size_t)(o_base + i) * HIDE + j]);
        }
#pragma unroll
        for (int off = 16; off > 0; off >>= 1) {
#pragma unroll
            for (int i = 0; i < 8; i++)
                acc[i] += __shfl_xor_sync(0xFFFFFFFFu, acc[i], off);
        }
        if (lane == 0) {
#pragma unroll
            for (int i = 0; i < 8; i++)
                out[b * OP + o_base + i] = 1.0f / (1.0f + expf(-acc[i]));
        }
    }
}

extern "C" void kernel_launch(void* const* d_in, const int* in_sizes, int n_in,
                              void* d_out, int out_size) {
    const float* x  = (const float*)d_in[0];
    const float* W1 = (const float*)d_in[1];
    const float* A2 = (const float*)d_in[2];
    const float* w2 = (const float*)d_in[3];
    const float* w3 = (const float*)d_in[4];
    const float* W4 = (const float*)d_in[5];
    float* out = (float*)d_out;

    float* yscratch;
    cudaGetSymbolAddress((void**)&yscratch, g_y);

    // 0) warm weights into L2 as evict_last (triggers PDL immediately)
    prefetch_kernel<<<18, 256>>>(W1, A2, W4);

    // 1) pool, PDL-launched under the prefetch (no data dependency, so no
    //    grid-dependency sync inside)
    {
        cudaLaunchConfig_t cfg = {};
        cfg.gridDim = dim3(B * CIN);
        cfg.blockDim = dim3(256);
        cfg.stream = 0;
        cudaLaunchAttribute attr[1];
        attr[0].id = cudaLaunchAttributeProgrammaticStreamSerialization;
        attr[0].val.programmaticStreamSerializationAllowed = 1;
        cfg.attrs = attr;
        cfg.numAttrs = 1;
        cudaLaunchKernelEx(&cfg, pool_kernel, x, yscratch);
    }

    // 2) head, PDL-launched under the pool's drain
    {
        cudaLaunchConfig_t cfg = {};
        cfg.gridDim = dim3(B);
        cfg.blockDim = dim3(1024);
        cfg.stream = 0;
        cudaLaunchAttribute attr[1];
        attr[0].id = cudaLaunchAttributeProgrammaticStreamSerialization;
        attr[0].val.programmaticStreamSerializationAllowed = 1;
        cfg.attrs = attr;
        cfg.numAttrs = 1;
        cudaLaunchKernelEx(&cfg, head_kernel, (const float*)yscratch, W1, A2, w2, w3, W4, out);
    }
}